// round 4
// baseline (speedup 1.0000x reference)
#include <cuda_runtime.h>
#include <math.h>

#define NP   31752
#define D_   192
#define NA   256
#define LMB  0.1f
#define NIT  25
#define NSQ  11
#define T_   72
#define NTHR 576
#define NCTA 441

typedef unsigned long long ull;

// ---------------- static device scratch (no cudaMalloc) ----------------
__device__ float g_A[NA * D_];     // normalized dictionary, row-major [a][d]
__device__ float g_At[D_ * NA];    // transposed dictionary [d][a]
__device__ float g_X[NA * NA];     // Gram
__device__ float g_Ma[NA * NA];
__device__ float g_Mb[NA * NA];
__device__ float g_f[16];
__device__ float g_params[4];      // L, 1/L, lambda/L
__device__ float g_mean[NP];
__device__ float g_pt[D_ * NP];    // centered patches, d-major [d][n]
__device__ float g_rec[NP * D_];   // reconstruction [n][d]

__device__ __forceinline__ const float* pick(int id) {
    return id == 0 ? g_A : id == 1 ? g_X : id == 2 ? g_Ma : g_Mb;
}

// ---------------- f32x2 helpers ----------------
__device__ __forceinline__ ull pk2(float a, float b) {
    ull r; asm("mov.b64 %0, {%1,%2};" : "=l"(r) : "f"(a), "f"(b)); return r;
}
__device__ __forceinline__ ull f2fma(ull a, ull b, ull c) {
    ull d; asm("fma.rn.f32x2 %0, %1, %2, %3;" : "=l"(d) : "l"(a), "l"(b), "l"(c)); return d;
}
__device__ __forceinline__ void up2(ull v, float& lo, float& hi) {
    asm("mov.b64 {%0,%1}, %2;" : "=f"(lo), "=f"(hi) : "l"(v));
}

// ---------------- 1. normalize atoms ----------------
__global__ void k_norm(const float* __restrict__ atoms) {
    __shared__ float red[256];
    int r = blockIdx.x, t = threadIdx.x;
    float v = (t < D_) ? atoms[r * D_ + t] : 0.f;
    red[t] = v * v;
    __syncthreads();
    for (int o = 128; o > 0; o >>= 1) { if (t < o) red[t] += red[t + o]; __syncthreads(); }
    float inv = 1.0f / sqrtf(red[0]);
    if (t < D_) { float a = v * inv; g_A[r * D_ + t] = a; g_At[t * NA + r] = a; }
}

// ---------------- 2. Out = scale * In In^T   (In: [256][K] row-major) ----------------
__global__ void k_mmT(int inId, int outId, int K, int fidx) {
    __shared__ float As[16][17], Bs[16][17];
    const float* In = pick(inId);
    float* Out = (float*)pick(outId);
    int tx = threadIdx.x, ty = threadIdx.y;
    int row = blockIdx.y * 16 + ty, col0 = blockIdx.x * 16;
    float acc = 0.f;
    for (int kt = 0; kt < K; kt += 16) {
        As[ty][tx] = In[row * K + kt + tx];
        Bs[ty][tx] = In[(col0 + ty) * K + kt + tx];
        __syncthreads();
#pragma unroll
        for (int kk = 0; kk < 16; kk++) acc += As[ty][kk] * Bs[tx][kk];
        __syncthreads();
    }
    float s = 1.f;
    if (fidx >= 0) { float f = g_f[fidx]; s = 1.f / (f * f); }
    Out[row * NA + col0 + tx] = acc * s;
}

// ---------------- 3. Frobenius norm ----------------
__global__ void k_frob(int srcId, int fidx) {
    __shared__ float red[256];
    const float* M = pick(srcId);
    int t = threadIdx.x;
    float s = 0.f;
    for (int i = t; i < NA * NA; i += 256) { float v = M[i]; s += v * v; }
    red[t] = s;
    __syncthreads();
    for (int o = 128; o > 0; o >>= 1) { if (t < o) red[t] += red[t + o]; __syncthreads(); }
    if (t == 0) g_f[fidx] = sqrtf(red[0]);
}

// ---------------- 4. spectral norm assembly ----------------
__global__ void k_param(int srcId) {
    __shared__ float red[256];
    const float* M = pick(srcId);
    int t = threadIdx.x;
    red[t] = M[t * NA + t];
    __syncthreads();
    for (int o = 128; o > 0; o >>= 1) { if (t < o) red[t] += red[t + o]; __syncthreads(); }
    if (t == 0) {
        double lg = log((double)red[0]);
        for (int j = 1; j <= NSQ; j++)
            lg += (double)(1 << (NSQ + 1 - j)) * log((double)g_f[j]);
        double L = exp(lg / (double)(1 << NSQ));
        g_params[0] = (float)L;
        g_params[1] = (float)(1.0 / L);
        g_params[2] = (float)((double)LMB / L);
    }
}

// ---------------- 5. per-patch mean ----------------
__global__ void k_mean(const float* __restrict__ y) {
    int n = blockIdx.x * 8 + (threadIdx.x >> 5);
    int l = threadIdx.x & 31;
    int b = n / 3969, r = n % 3969, i = r / 63, j = r % 63;
    float s = 0.f;
    for (int d = l; d < D_; d += 32) {
        int ch = d >> 6, u = (d >> 3) & 7, v = d & 7;
        s += y[((b * 3 + ch) * 256 + i * 4 + u) * 256 + j * 4 + v];
    }
    for (int o = 16; o > 0; o >>= 1) s += __shfl_xor_sync(0xffffffffu, s, o);
    if (l == 0) g_mean[n] = s * (1.f / 192.f);
}

// ---------------- 6. centered patches, d-major ----------------
__global__ void k_pt(const float* __restrict__ y) {
    int n = blockIdx.x * 256 + threadIdx.x;
    if (n >= NP) return;
    int d = blockIdx.y;
    int b = n / 3969, r = n % 3969, i = r / 63, j = r % 63;
    int ch = d >> 6, u = (d >> 3) & 7, v = d & 7;
    g_pt[d * NP + n] = y[((b * 3 + ch) * 256 + i * 4 + u) * 256 + j * 4 + v] - g_mean[n];
}

// ---------------- fused q + ISTA + rec ----------------
// SMEM layout (floats): cs[256*72] | qs[256*72] | Xsh[2*16*256] | mean[72]
#define CS_OFF 0
#define QS_OFF (256 * T_)
#define XS_OFF (2 * 256 * T_)
#define MS_OFF (XS_OFF + 2 * 16 * 256)
#define SM_FLOATS (MS_OFF + T_)

// acc += slab-streamed GEMM:  acc rows r0..r0+7 (as 4 f32x2 pairs) x cols j0..j0+3
// gsrc: nslab slabs of 16x256 (row-major, coalesced); csrc: k-major [16*nslab][T_]
__device__ __forceinline__ void slab_gemm(ull acc[4][4], const float* __restrict__ gsrc,
                                          const float* csrc, float* Xsh,
                                          int nslab, int r0, int j0, int tid) {
    for (int i = tid; i < 1024; i += NTHR) {
        int kk = i >> 6, r4 = (i & 63) << 2;
        *(float4*)&Xsh[kk * 256 + r4] = *(const float4*)&gsrc[kk * 256 + r4];
    }
    __syncthreads();
    for (int s = 0; s < nslab; s++) {
        float4 pf0, pf1;
        bool have1 = false;
        if (s + 1 < nslab) {
            const float* src = gsrc + (s + 1) * 4096;
            int kk = tid >> 6, r4 = (tid & 63) << 2;
            pf0 = *(const float4*)&src[kk * 256 + r4];
            if (tid + NTHR < 1024) {
                int i1 = tid + NTHR; kk = i1 >> 6; r4 = (i1 & 63) << 2;
                pf1 = *(const float4*)&src[kk * 256 + r4];
                have1 = true;
            }
        }
        const float* Xb = Xsh + (s & 1) * 4096;
        const float* cb = csrc + s * 16 * T_;
#pragma unroll
        for (int kk = 0; kk < 16; kk++) {
            ulonglong2 xa = *(const ulonglong2*)&Xb[kk * 256 + r0];
            ulonglong2 xb = *(const ulonglong2*)&Xb[kk * 256 + r0 + 4];
            float4 cv = *(const float4*)&cb[kk * T_ + j0];
            ull c0 = pk2(cv.x, cv.x), c1 = pk2(cv.y, cv.y);
            ull c2 = pk2(cv.z, cv.z), c3 = pk2(cv.w, cv.w);
            acc[0][0] = f2fma(xa.x, c0, acc[0][0]); acc[1][0] = f2fma(xa.y, c0, acc[1][0]);
            acc[2][0] = f2fma(xb.x, c0, acc[2][0]); acc[3][0] = f2fma(xb.y, c0, acc[3][0]);
            acc[0][1] = f2fma(xa.x, c1, acc[0][1]); acc[1][1] = f2fma(xa.y, c1, acc[1][1]);
            acc[2][1] = f2fma(xb.x, c1, acc[2][1]); acc[3][1] = f2fma(xb.y, c1, acc[3][1]);
            acc[0][2] = f2fma(xa.x, c2, acc[0][2]); acc[1][2] = f2fma(xa.y, c2, acc[1][2]);
            acc[2][2] = f2fma(xb.x, c2, acc[2][2]); acc[3][2] = f2fma(xb.y, c2, acc[3][2]);
            acc[0][3] = f2fma(xa.x, c3, acc[0][3]); acc[1][3] = f2fma(xa.y, c3, acc[1][3]);
            acc[2][3] = f2fma(xb.x, c3, acc[2][3]); acc[3][3] = f2fma(xb.y, c3, acc[3][3]);
        }
        __syncthreads();
        if (s + 1 < nslab) {
            float* dst = Xsh + ((s + 1) & 1) * 4096;
            int kk = tid >> 6, r4 = (tid & 63) << 2;
            *(float4*)&dst[kk * 256 + r4] = pf0;
            if (have1) {
                int i1 = tid + NTHR; kk = i1 >> 6; r4 = (i1 & 63) << 2;
                *(float4*)&dst[kk * 256 + r4] = pf1;
            }
            __syncthreads();
        }
    }
}

__global__ void __launch_bounds__(NTHR, 1) k_fused() {
    extern __shared__ float sm[];
    float* cs = sm + CS_OFF;
    float* qs = sm + QS_OFF;
    float* Xsh = sm + XS_OFF;
    float* msh = sm + MS_OFF;
    const int tid = threadIdx.x;
    const int n0 = blockIdx.x * T_;
    const int cg = tid % 18, rg = tid / 18;
    const int j0 = cg * 4, r0 = rg * 8;
    const float invL = g_params[1], thr = g_params[2];

    // load centered patch tile (d-major) into cs area; mean tile
    for (int i = tid; i < D_ * T_; i += NTHR)
        cs[i] = g_pt[(i / T_) * NP + n0 + (i % T_)];
    if (tid < T_) msh[tid] = g_mean[n0 + tid];
    __syncthreads();

    ull acc[4][4];
#pragma unroll
    for (int a = 0; a < 4; a++)
#pragma unroll
        for (int b = 0; b < 4; b++) acc[a][b] = 0ull;

    // ---- prologue: qs = A @ p^T  (K = 192, slabs from g_At) ----
    slab_gemm(acc, g_At, cs, Xsh, 12, r0, j0, tid);
#pragma unroll
    for (int rp = 0; rp < 4; rp++)
#pragma unroll
        for (int jj = 0; jj < 4; jj++) {
            float lo, hi; up2(acc[rp][jj], lo, hi);
            qs[(r0 + 2 * rp) * T_ + j0 + jj] = lo;
            qs[(r0 + 2 * rp + 1) * T_ + j0 + jj] = hi;
        }
    __syncthreads();
    for (int i = tid; i < 256 * T_; i += NTHR) cs[i] = 0.f;
    __syncthreads();

    // ---- 25 ISTA iterations ----
    for (int it = 0; it < NIT; it++) {
#pragma unroll
        for (int a = 0; a < 4; a++)
#pragma unroll
            for (int b = 0; b < 4; b++) acc[a][b] = 0ull;
        if (it > 0) slab_gemm(acc, g_X, cs, Xsh, 16, r0, j0, tid);
        // all cross-thread reads of cs are behind slab_gemm's final barrier
#pragma unroll
        for (int rp = 0; rp < 4; rp++)
#pragma unroll
            for (int jj = 0; jj < 4; jj++) {
                float lo, hi; up2(acc[rp][jj], lo, hi);
                int ra = r0 + 2 * rp, rb = ra + 1;
                float va = cs[ra * T_ + j0 + jj] - (lo - qs[ra * T_ + j0 + jj]) * invL;
                float vb = cs[rb * T_ + j0 + jj] - (hi - qs[rb * T_ + j0 + jj]) * invL;
                float aa = fabsf(va) - thr;
                float ab = fabsf(vb) - thr;
                cs[ra * T_ + j0 + jj] = aa > 0.f ? copysignf(aa, va) : 0.f;
                cs[rb * T_ + j0 + jj] = ab > 0.f ? copysignf(ab, vb) : 0.f;
            }
        __syncthreads();
    }

    // ---- epilogue: rec = c^T A + mean  (K = 256 atoms, slabs of g_A [16][192]) ----
    {
        const int dg = tid & 31, jg = tid >> 5;
        const int d0 = dg * 6, j0e = jg * 4;
        ull racc[4][3];
#pragma unroll
        for (int a = 0; a < 4; a++)
#pragma unroll
            for (int b = 0; b < 3; b++) racc[a][b] = 0ull;
        for (int i = tid; i < 768; i += NTHR) {
            int aa = i / 48, dd = (i % 48) * 4;
            *(float4*)&Xsh[aa * 192 + dd] = *(const float4*)&g_A[aa * 192 + dd];
        }
        __syncthreads();
        for (int s = 0; s < 16; s++) {
            float4 pf0, pf1;
            bool have1 = false;
            if (s + 1 < 16) {
                const float* src = g_A + (s + 1) * 3072;
                int aa = tid / 48, dd = (tid % 48) * 4;
                pf0 = *(const float4*)&src[aa * 192 + dd];
                if (tid + NTHR < 768) {
                    int i1 = tid + NTHR; aa = i1 / 48; dd = (i1 % 48) * 4;
                    pf1 = *(const float4*)&src[aa * 192 + dd];
                    have1 = true;
                }
            }
            const float* Ab = Xsh + (s & 1) * 3072;
#pragma unroll
            for (int kk = 0; kk < 16; kk++) {
                int a = s * 16 + kk;
                float4 cv = *(const float4*)&cs[a * T_ + j0e];
                ull ap0 = *(const ull*)&Ab[kk * 192 + d0];
                ull ap1 = *(const ull*)&Ab[kk * 192 + d0 + 2];
                ull ap2 = *(const ull*)&Ab[kk * 192 + d0 + 4];
                ull c0 = pk2(cv.x, cv.x), c1 = pk2(cv.y, cv.y);
                ull c2 = pk2(cv.z, cv.z), c3 = pk2(cv.w, cv.w);
                racc[0][0] = f2fma(ap0, c0, racc[0][0]); racc[0][1] = f2fma(ap1, c0, racc[0][1]); racc[0][2] = f2fma(ap2, c0, racc[0][2]);
                racc[1][0] = f2fma(ap0, c1, racc[1][0]); racc[1][1] = f2fma(ap1, c1, racc[1][1]); racc[1][2] = f2fma(ap2, c1, racc[1][2]);
                racc[2][0] = f2fma(ap0, c2, racc[2][0]); racc[2][1] = f2fma(ap1, c2, racc[2][1]); racc[2][2] = f2fma(ap2, c2, racc[2][2]);
                racc[3][0] = f2fma(ap0, c3, racc[3][0]); racc[3][1] = f2fma(ap1, c3, racc[3][1]); racc[3][2] = f2fma(ap2, c3, racc[3][2]);
            }
            __syncthreads();
            if (s + 1 < 16) {
                float* dst = Xsh + ((s + 1) & 1) * 3072;
                int aa = tid / 48, dd = (tid % 48) * 4;
                *(float4*)&dst[aa * 192 + dd] = pf0;
                if (have1) {
                    int i1 = tid + NTHR; aa = i1 / 48; dd = (i1 % 48) * 4;
                    *(float4*)&dst[aa * 192 + dd] = pf1;
                }
                __syncthreads();
            }
        }
#pragma unroll
        for (int jj = 0; jj < 4; jj++) {
            int n = n0 + j0e + jj;
            float m = msh[j0e + jj];
            float* o = g_rec + n * D_ + d0;
#pragma unroll
            for (int dp = 0; dp < 3; dp++) {
                float lo, hi; up2(racc[jj][dp], lo, hi);
                o[2 * dp] = lo + m;
                o[2 * dp + 1] = hi + m;
            }
        }
    }
}

// ---------------- overlap-add + count division ----------------
__global__ void k_out(float* __restrict__ out) {
    int idx = blockIdx.x * 256 + threadIdx.x;
    if (idx >= 8 * 3 * 256 * 256) return;
    int w = idx & 255, h = (idx >> 8) & 255;
    int ch = (idx >> 16) % 3, b = (idx >> 16) / 3;
    int ihi = h >> 2; if (ihi > 62) ihi = 62;
    int ilo = (h >= 7) ? ((h - 4) >> 2) : 0;
    int jhi = w >> 2; if (jhi > 62) jhi = 62;
    int jlo = (w >= 7) ? ((w - 4) >> 2) : 0;
    float s = 0.f;
    int cnt = 0;
    for (int i = ilo; i <= ihi; i++) {
        int u = h - 4 * i;
        for (int j = jlo; j <= jhi; j++) {
            int v = w - 4 * j;
            int n = b * 3969 + i * 63 + j;
            s += g_rec[n * D_ + ch * 64 + u * 8 + v];
            cnt++;
        }
    }
    out[idx] = s / (float)cnt;
}

// ---------------- host launcher ----------------
extern "C" void kernel_launch(void* const* d_in, const int* in_sizes, int n_in,
                              void* d_out, int out_size) {
    const float* y = (const float*)d_in[0];
    const float* atoms = (const float*)d_in[1];
    if (n_in >= 2 && in_sizes[0] < in_sizes[1]) {  // defensive input ordering
        y = (const float*)d_in[1];
        atoms = (const float*)d_in[0];
    }
    float* out = (float*)d_out;

    k_norm<<<NA, 256>>>(atoms);
    k_mmT<<<dim3(16, 16), dim3(16, 16)>>>(0, 1, D_, -1);  // X = A A^T
    int src = 1;
    for (int j = 1; j <= NSQ; j++) {
        int dst = (j & 1) ? 2 : 3;
        k_frob<<<1, 256>>>(src, j);
        k_mmT<<<dim3(16, 16), dim3(16, 16)>>>(src, dst, NA, j);
        src = dst;
    }
    k_param<<<1, 256>>>(src);
    k_mean<<<NP / 8, 256>>>(y);
    k_pt<<<dim3(125, D_), 256>>>(y);

    cudaFuncSetAttribute(k_fused, cudaFuncAttributeMaxDynamicSharedMemorySize,
                         SM_FLOATS * (int)sizeof(float));
    k_fused<<<NCTA, NTHR, SM_FLOATS * sizeof(float)>>>();

    k_out<<<(8 * 3 * 256 * 256 + 255) / 256, 256>>>(out);
}